// round 9
// baseline (speedup 1.0000x reference)
#include <cuda_runtime.h>
#include <math.h>

// DictionaryMatchingTv — bit-replicated fp32 nearest-atom search.
// R9: LDS.128 dictionary loads (5 LDS/pair vs 9 — R8 profile showed L1=78.6%
// was the binding pipe) + ballot-based mask in prep (kills 5us serial scan).

#define MAX_D   4096
#define MAX_ETL 16
#define NPB     256   // pixels per block (K8 path)
#define NG      4     // dictionary chunks (K8 path)
#define THREADS 1024

typedef unsigned long long ull;

__device__ int   g_cols[MAX_ETL];
__device__ int   g_ncols, g_kpad;

// K=8 path: pair-interleaved dict (a0k,a1k per k), flat d2 per atom (padded)
__device__ float g_dbp[((MAX_D + 1) / 2) * 16];
__device__ float g_d2p[MAX_D + 1];

// K=16 fallback path
__device__ float g_db16[MAX_D * MAX_ETL];
__device__ float g_d2_16[MAX_D];

// ---- packed f32x2 helpers (per-lane IEEE rn, identical to scalar) --------
__device__ __forceinline__ ull pack2(float lo, float hi) {
    ull r; asm("mov.b64 %0, {%1, %2};" : "=l"(r) : "f"(lo), "f"(hi)); return r;
}
__device__ __forceinline__ void unpack2(ull v, float& lo, float& hi) {
    asm("mov.b64 {%0, %1}, %2;" : "=f"(lo), "=f"(hi) : "l"(v));
}
__device__ __forceinline__ ull ffma2(ull a, ull b, ull c) {
    ull d; asm("fma.rn.f32x2 %0, %1, %2, %3;" : "=l"(d) : "l"(a), "l"(b), "l"(c)); return d;
}
__device__ __forceinline__ ull fadd2(ull a, ull b) {
    ull d; asm("add.rn.f32x2 %0, %1, %2;" : "=l"(d) : "l"(a), "l"(b)); return d;
}

// ---------------------------------------------------------------------------
// Mask via warp ballot (parallel; order = ascending lane == serial scan).
// Call from full warp 0; writes s_cols/s_ncols.
// ---------------------------------------------------------------------------
__device__ __forceinline__ void ballot_mask(const float* __restrict__ delta,
                                            int etl, int* s_cols, int* s_ncols) {
    const int lane = threadIdx.x;             // caller guarantees tid < 32
    bool p = false;
    if (lane < etl && lane < MAX_ETL)
        p = (__fmul_rn(delta[lane], 1e-3f) < 1e-3f);
    const unsigned m = __ballot_sync(0xffffffffu, p);
    if (p) s_cols[__popc(m & ((1u << lane) - 1u))] = lane;
    if (lane == 0) *s_ncols = __popc(m);
}

// ---------------------------------------------------------------------------
// Prep: fully parallel; ballot mask + per-atom normalize + pair-interleave.
// ---------------------------------------------------------------------------
__global__ void __launch_bounds__(128)
prep_kernel(const float* __restrict__ delta, const float* __restrict__ db_mag,
            int D, int etl) {
    __shared__ int s_cols[MAX_ETL];
    __shared__ int s_ncols;
    if (threadIdx.x < 32) ballot_mask(delta, etl, s_cols, &s_ncols);
    __syncthreads();
    const int ncols = s_ncols;
    const int kp    = (ncols <= 8) ? 8 : 16;
    if (blockIdx.x == 0 && threadIdx.x == 0) {
        for (int k = 0; k < ncols; k++) g_cols[k] = s_cols[k];
        g_ncols = ncols;
        g_kpad  = kp;
    }
    const int Dpad = (D + 1) & ~1;

    for (int a = blockIdx.x * blockDim.x + threadIdx.x; a < Dpad;
         a += gridDim.x * blockDim.x) {
        const int d = (a < D) ? a : D - 1;          // pad = duplicate last atom
        float x[MAX_ETL];
#pragma unroll
        for (int k = 0; k < MAX_ETL; k++)
            x[k] = (k < ncols) ? db_mag[d * etl + s_cols[k]] : 0.f;
        float ss = 0.f;
#pragma unroll
        for (int k = 0; k < MAX_ETL; k++) ss = __fadd_rn(ss, __fmul_rn(x[k], x[k]));
        const float nn = __fsqrt_rn(ss);
        float v[MAX_ETL]; float d2 = 0.f;
#pragma unroll
        for (int k = 0; k < MAX_ETL; k++) {
            v[k] = (nn > 0.f) ? __fdiv_rn(x[k], nn) : 0.f;
            d2 = __fadd_rn(d2, __fmul_rn(v[k], v[k]));
        }
        if (kp == 8) {
            const int base = (a >> 1) * 16 + (a & 1);
#pragma unroll
            for (int k = 0; k < 8; k++) g_dbp[base + 2 * k] = v[k];
            g_d2p[a] = d2;
        } else if (a < D) {
#pragma unroll
            for (int k = 0; k < MAX_ETL; k++) g_db16[d * MAX_ETL + k] = v[k];
            g_d2_16[d] = d2;
        }
    }
}

// ---------------------------------------------------------------------------
// Signal prep (two-stage normalization, exact fp32 replication).
// ---------------------------------------------------------------------------
template <int K>
__device__ __forceinline__ void prep_signal(const float* __restrict__ sig,
                                            int n, bool active, int etl,
                                            const int* s_cols, int ncols,
                                            float* v, float& s2) {
    float raw[MAX_ETL];
#pragma unroll
    for (int e = 0; e < MAX_ETL; e++)
        raw[e] = (active && e < etl) ? sig[n * etl + e] : 0.f;
    float ss1 = 0.f;
#pragma unroll
    for (int e = 0; e < MAX_ETL; e++) ss1 = __fadd_rn(ss1, __fmul_rn(raw[e], raw[e]));
    const float n1 = __fsqrt_rn(ss1);
    float t[K];
#pragma unroll
    for (int k = 0; k < K; k++) {
        t[k] = 0.f;
        if (k < ncols) t[k] = (n1 > 0.f) ? __fdiv_rn(raw[s_cols[k]], n1) : 0.f;
    }
    float ss2 = 0.f;
#pragma unroll
    for (int k = 0; k < K; k++) ss2 = __fadd_rn(ss2, __fmul_rn(t[k], t[k]));
    const float n2 = __fsqrt_rn(ss2);
#pragma unroll
    for (int k = 0; k < K; k++) v[k] = (n2 > 0.f) ? __fdiv_rn(t[k], n2) : 0.f;
    s2 = 0.f;
#pragma unroll
    for (int k = 0; k < K; k++) s2 = __fadd_rn(s2, __fmul_rn(v[k], v[k]));
}

// ---------------------------------------------------------------------------
// Fused worker: one launch, internal K8/K16 dispatch.
// ---------------------------------------------------------------------------
__global__ void __launch_bounds__(THREADS, 1)
match_kernel(const float* __restrict__ sig,
             const float* __restrict__ t2s,
             const float* __restrict__ b1s,
             float* __restrict__ out,
             int Npix, int D, int etl) {
    extern __shared__ char smem_raw[];
    __shared__ int s_cols[MAX_ETL];
    __shared__ int s_ncols;

    const int tid = threadIdx.x;
    if (tid < MAX_ETL) s_cols[tid] = g_cols[tid];
    if (tid == 0) s_ncols = g_ncols;

    if (g_kpad == 8) {
        // ================= K8 path =================
        const int P = (D + 1) >> 1;             // atom pairs (padded)
        float* s_db = (float*)smem_raw;         // P*16 floats, pair-interleaved
        float* s_d2 = s_db + P * 16;            // 2*P floats
        float* s_bu = s_d2 + 2 * P;
        int*   s_bi = (int*)(s_bu + NG * NPB);

        const int px  = tid & (NPB - 1);
        const int grp = tid >> 8;               // 0..3

        {
            const float4* src = (const float4*)g_dbp;
            float4* dst = (float4*)s_db;
            for (int i = tid; i < P * 4; i += THREADS) dst[i] = src[i];
            for (int i = tid; i < 2 * P; i += THREADS) s_d2[i] = g_d2p[i];
        }
        __syncthreads();

        const int n = blockIdx.x * NPB + px;
        const bool active = (n < Npix);

        float v[8]; float s2;
        prep_signal<8>(sig, n, active, etl, s_cols, s_ncols, v, s2);
        ull vk2[8];
#pragma unroll
        for (int k = 0; k < 8; k++) vk2[k] = pack2(v[k], v[k]);
        const ull s2p  = pack2(s2, s2);
        const ull neg2 = pack2(-2.f, -2.f);
        __syncthreads();

        const int Lp   = (P + NG - 1) / NG;
        const int myp0 = grp * Lp;
        const int myp1 = min(myp0 + Lp, P);

        float bU = INFINITY;
        int   bA = 0;

        // LDS.128 dict loads: 4 x ulonglong2 per pair (halves are aligned
        // register pairs -> feed FFMA2 directly, no repack).
        const ulonglong2* pq = (const ulonglong2*)s_db + (size_t)myp0 * 4;
#pragma unroll 2
        for (int p = myp0; p < myp1; p++, pq += 4) {
            const ulonglong2 q0 = pq[0];
            const ulonglong2 q1 = pq[1];
            const ulonglong2 q2 = pq[2];
            const ulonglong2 q3 = pq[3];
            ull acc = 0ull;
            acc = ffma2(q0.x, vk2[0], acc);
            acc = ffma2(q0.y, vk2[1], acc);
            acc = ffma2(q1.x, vk2[2], acc);
            acc = ffma2(q1.y, vk2[3], acc);
            acc = ffma2(q2.x, vk2[4], acc);
            acc = ffma2(q2.y, vk2[5], acc);
            acc = ffma2(q3.x, vk2[6], acc);
            acc = ffma2(q3.y, vk2[7], acc);
            const ull d2pair = *(const ull*)&s_d2[2 * p];
            const ull h  = fadd2(d2pair, s2p);
            const ull u2 = ffma2(neg2, acc, h);     // exact: 2*dot unrounded
            float u0, u1; unpack2(u2, u0, u1);
            u0 = fmaxf(u0, 0.f);
            u1 = fmaxf(u1, 0.f);
            if (u0 < bU) { bU = u0; bA = 2 * p; }   // strict < -> first min
            if (u1 < bU) { bU = u1; bA = 2 * p + 1; }
        }
        if (bA >= D) bA = D - 1;                    // pad lane = dup of last

        s_bu[grp * NPB + px] = bU;
        s_bi[grp * NPB + px] = bA;
        __syncthreads();

        if (grp == 0 && active) {
            float bu = s_bu[px]; int bi = s_bi[px];
#pragma unroll
            for (int g = 1; g < NG; g++) {
                const float u = s_bu[g * NPB + px];
                const int   i = s_bi[g * NPB + px];
                if (u < bu || (u == bu && i < bi)) { bu = u; bi = i; }
            }
            out[n]            = t2s[bi];
            out[Npix + n]     = b1s[bi];
            out[2 * Npix + n] = __fsqrt_rn(bu);
        }
    } else {
        // ================= K16 fallback (tiled, 1024 threads) =============
        constexpr int K = 16, TS = 512;
        float* s_db = (float*)smem_raw;          // TS*K floats
        float* s_d2 = s_db + TS * K;             // TS floats
        __syncthreads();                         // s_cols ready

        const int n = blockIdx.x * THREADS + tid;
        const bool active = (n < Npix);

        float v[K]; float s2;
        prep_signal<K>(sig, n, active, etl, s_cols, s_ncols, v, s2);

        float bestU = INFINITY; int bestI = 0;
        for (int tile0 = 0; tile0 < D; tile0 += TS) {
            const int cnt = min(TS, D - tile0);
            __syncthreads();
            const float4* src = (const float4*)&g_db16[tile0 * K];
            float4* dst = (float4*)s_db;
            for (int idx = tid; idx < cnt * K / 4; idx += THREADS) dst[idx] = src[idx];
            for (int idx = tid; idx < cnt; idx += THREADS) s_d2[idx] = g_d2_16[tile0 + idx];
            __syncthreads();
            for (int aa = 0; aa < cnt; aa++) {
                const float4* p = (const float4*)&s_db[aa * K];
                float dot = 0.f;
#pragma unroll
                for (int q = 0; q < K / 4; q++) {
                    float4 w = p[q];
                    dot = __fmaf_rn(w.x, v[4 * q + 0], dot);
                    dot = __fmaf_rn(w.y, v[4 * q + 1], dot);
                    dot = __fmaf_rn(w.z, v[4 * q + 2], dot);
                    dot = __fmaf_rn(w.w, v[4 * q + 3], dot);
                }
                const float u = fmaxf(__fmaf_rn(-2.f, dot, __fadd_rn(s_d2[aa], s2)), 0.f);
                if (u < bestU) { bestU = u; bestI = tile0 + aa; }
            }
        }
        if (active) {
            out[n]            = t2s[bestI];
            out[Npix + n]     = b1s[bestI];
            out[2 * Npix + n] = __fsqrt_rn(bestU);
        }
    }
}

// ---------------------------------------------------------------------------
extern "C" void kernel_launch(void* const* d_in, const int* in_sizes, int n_in,
                              void* d_out, int out_size) {
    const float* sig    = (const float*)d_in[0];
    const float* db_mag = (const float*)d_in[1];
    const float* t2s    = (const float*)d_in[2];
    const float* b1s    = (const float*)d_in[3];
    const float* delta  = (const float*)d_in[4];

    const int etl  = in_sizes[4];
    const int D    = in_sizes[1] / etl;
    const int Npix = in_sizes[0] / etl;
    float* out = (float*)d_out;

    // dynamic smem: max of K8 layout and K16 tile layout
    const int P = (D + 1) / 2;
    const size_t dyn8  = (size_t)(P * 16 + 2 * P + NG * NPB) * 4
                       + (size_t)(NG * NPB) * 4;
    const size_t dyn16 = (size_t)(512 * 16 + 512) * 4;
    const size_t dyn   = (dyn8 > dyn16) ? dyn8 : dyn16;
    cudaFuncSetAttribute(match_kernel,
                         cudaFuncAttributeMaxDynamicSharedMemorySize, (int)dyn);

    const int grid = (Npix + NPB - 1) / NPB;
    prep_kernel<<<32, 128>>>(delta, db_mag, D, etl);
    match_kernel<<<grid, THREADS, dyn>>>(sig, t2s, b1s, out, Npix, D, etl);
}

// round 10
// speedup vs baseline: 1.1216x; 1.1216x over previous
#include <cuda_runtime.h>
#include <math.h>

// DictionaryMatchingTv — bit-replicated fp32 nearest-atom search.
// R10: PX=2 pixels/thread at THREADS=512 (128-reg cap -> no spill). The R8/R9
// profile showed smem-return bytes/lane binding at 78.6%; sharing the dict
// stream across 2 pixels halves it. FMA floor (~42us) becomes the binder.

#define MAX_D   4096
#define MAX_ETL 16
#define NPB     256   // pixels per block
#define NSLOT   128   // pixel slots (each thread = 2 pixels: slot, slot+128)
#define NG      4     // dictionary chunks
#define THREADS 512   // NSLOT * NG

typedef unsigned long long ull;

__device__ int   g_cols[MAX_ETL];
__device__ int   g_ncols, g_kpad;

// K=8 path: pair-interleaved dict (a0k,a1k per k), flat d2 per atom (padded)
__device__ float g_dbp[((MAX_D + 1) / 2) * 16];
__device__ float g_d2p[MAX_D + 1];

// K=16 fallback path
__device__ float g_db16[MAX_D * MAX_ETL];
__device__ float g_d2_16[MAX_D];

// ---- packed f32x2 helpers (per-lane IEEE rn, identical to scalar) --------
__device__ __forceinline__ ull pack2(float lo, float hi) {
    ull r; asm("mov.b64 %0, {%1, %2};" : "=l"(r) : "f"(lo), "f"(hi)); return r;
}
__device__ __forceinline__ void unpack2(ull v, float& lo, float& hi) {
    asm("mov.b64 {%0, %1}, %2;" : "=f"(lo), "=f"(hi) : "l"(v));
}
__device__ __forceinline__ ull ffma2(ull a, ull b, ull c) {
    ull d; asm("fma.rn.f32x2 %0, %1, %2, %3;" : "=l"(d) : "l"(a), "l"(b), "l"(c)); return d;
}
__device__ __forceinline__ ull fadd2(ull a, ull b) {
    ull d; asm("add.rn.f32x2 %0, %1, %2;" : "=l"(d) : "l"(a), "l"(b)); return d;
}

// ---------------------------------------------------------------------------
// Mask via warp ballot (order = ascending lane == serial scan).
// ---------------------------------------------------------------------------
__device__ __forceinline__ void ballot_mask(const float* __restrict__ delta,
                                            int etl, int* s_cols, int* s_ncols) {
    const int lane = threadIdx.x;             // caller guarantees tid < 32
    bool p = false;
    if (lane < etl && lane < MAX_ETL)
        p = (__fmul_rn(delta[lane], 1e-3f) < 1e-3f);
    const unsigned m = __ballot_sync(0xffffffffu, p);
    if (p) s_cols[__popc(m & ((1u << lane) - 1u))] = lane;
    if (lane == 0) *s_ncols = __popc(m);
}

// ---------------------------------------------------------------------------
// Prep (parallel): mask + normalize + pair-interleave.
// ---------------------------------------------------------------------------
__global__ void __launch_bounds__(128)
prep_kernel(const float* __restrict__ delta, const float* __restrict__ db_mag,
            int D, int etl) {
    __shared__ int s_cols[MAX_ETL];
    __shared__ int s_ncols;
    if (threadIdx.x < 32) ballot_mask(delta, etl, s_cols, &s_ncols);
    __syncthreads();
    const int ncols = s_ncols;
    const int kp    = (ncols <= 8) ? 8 : 16;
    if (blockIdx.x == 0 && threadIdx.x == 0) {
        for (int k = 0; k < ncols; k++) g_cols[k] = s_cols[k];
        g_ncols = ncols;
        g_kpad  = kp;
    }
    const int Dpad = (D + 1) & ~1;

    for (int a = blockIdx.x * blockDim.x + threadIdx.x; a < Dpad;
         a += gridDim.x * blockDim.x) {
        const int d = (a < D) ? a : D - 1;          // pad = duplicate last atom
        float x[MAX_ETL];
#pragma unroll
        for (int k = 0; k < MAX_ETL; k++)
            x[k] = (k < ncols) ? db_mag[d * etl + s_cols[k]] : 0.f;
        float ss = 0.f;
#pragma unroll
        for (int k = 0; k < MAX_ETL; k++) ss = __fadd_rn(ss, __fmul_rn(x[k], x[k]));
        const float nn = __fsqrt_rn(ss);
        float v[MAX_ETL]; float d2 = 0.f;
#pragma unroll
        for (int k = 0; k < MAX_ETL; k++) {
            v[k] = (nn > 0.f) ? __fdiv_rn(x[k], nn) : 0.f;
            d2 = __fadd_rn(d2, __fmul_rn(v[k], v[k]));
        }
        if (kp == 8) {
            const int base = (a >> 1) * 16 + (a & 1);
#pragma unroll
            for (int k = 0; k < 8; k++) g_dbp[base + 2 * k] = v[k];
            g_d2p[a] = d2;
        } else if (a < D) {
#pragma unroll
            for (int k = 0; k < MAX_ETL; k++) g_db16[d * MAX_ETL + k] = v[k];
            g_d2_16[d] = d2;
        }
    }
}

// ---------------------------------------------------------------------------
// Signal prep (two-stage normalization, exact fp32 replication).
// ---------------------------------------------------------------------------
template <int K>
__device__ __forceinline__ void prep_signal(const float* __restrict__ sig,
                                            int n, bool active, int etl,
                                            const int* s_cols, int ncols,
                                            float* v, float& s2) {
    float raw[MAX_ETL];
#pragma unroll
    for (int e = 0; e < MAX_ETL; e++)
        raw[e] = (active && e < etl) ? sig[n * etl + e] : 0.f;
    float ss1 = 0.f;
#pragma unroll
    for (int e = 0; e < MAX_ETL; e++) ss1 = __fadd_rn(ss1, __fmul_rn(raw[e], raw[e]));
    const float n1 = __fsqrt_rn(ss1);
    float t[K];
#pragma unroll
    for (int k = 0; k < K; k++) {
        t[k] = 0.f;
        if (k < ncols) t[k] = (n1 > 0.f) ? __fdiv_rn(raw[s_cols[k]], n1) : 0.f;
    }
    float ss2 = 0.f;
#pragma unroll
    for (int k = 0; k < K; k++) ss2 = __fadd_rn(ss2, __fmul_rn(t[k], t[k]));
    const float n2 = __fsqrt_rn(ss2);
#pragma unroll
    for (int k = 0; k < K; k++) v[k] = (n2 > 0.f) ? __fdiv_rn(t[k], n2) : 0.f;
    s2 = 0.f;
#pragma unroll
    for (int k = 0; k < K; k++) s2 = __fadd_rn(s2, __fmul_rn(v[k], v[k]));
}

// ---------------------------------------------------------------------------
// Fused worker: one launch, internal K8/K16 dispatch.
// ---------------------------------------------------------------------------
__global__ void __launch_bounds__(THREADS, 1)
match_kernel(const float* __restrict__ sig,
             const float* __restrict__ t2s,
             const float* __restrict__ b1s,
             float* __restrict__ out,
             int Npix, int D, int etl) {
    extern __shared__ char smem_raw[];
    __shared__ int s_cols[MAX_ETL];
    __shared__ int s_ncols;

    const int tid = threadIdx.x;
    if (tid < MAX_ETL) s_cols[tid] = g_cols[tid];
    if (tid == 0) s_ncols = g_ncols;

    if (g_kpad == 8) {
        // ================= K8 path: 512 thr = 128 slots x 2 px x 4 chunks ==
        const int P = (D + 1) >> 1;             // atom pairs (padded)
        float* s_db = (float*)smem_raw;         // P*16 floats, pair-interleaved
        float* s_d2 = s_db + P * 16;            // 2*P floats
        float* s_bu = s_d2 + 2 * P;             // NG*NPB
        int*   s_bi = (int*)(s_bu + NG * NPB);  // NG*NPB

        const int slot = tid & (NSLOT - 1);     // 0..127
        const int grp  = tid >> 7;              // 0..3

        {
            const float4* src = (const float4*)g_dbp;
            float4* dst = (float4*)s_db;
            for (int i = tid; i < P * 4; i += THREADS) dst[i] = src[i];
            for (int i = tid; i < 2 * P; i += THREADS) s_d2[i] = g_d2p[i];
        }
        __syncthreads();

        const int n0 = blockIdx.x * NPB + slot;        // pixel A
        const int n1 = n0 + NSLOT;                     // pixel B
        const bool act0 = (n0 < Npix);
        const bool act1 = (n1 < Npix);

        float va[8], vb[8], s2a, s2b;
        prep_signal<8>(sig, n0, act0, etl, s_cols, s_ncols, va, s2a);
        prep_signal<8>(sig, n1, act1, etl, s_cols, s_ncols, vb, s2b);
        ull vka[8], vkb[8];
#pragma unroll
        for (int k = 0; k < 8; k++) { vka[k] = pack2(va[k], va[k]); vkb[k] = pack2(vb[k], vb[k]); }
        const ull s2pa = pack2(s2a, s2a);
        const ull s2pb = pack2(s2b, s2b);
        const ull neg2 = pack2(-2.f, -2.f);
        __syncthreads();

        const int Lp   = (P + NG - 1) / NG;
        const int myp0 = grp * Lp;
        const int myp1 = min(myp0 + Lp, P);

        float bU0 = INFINITY, bU1 = INFINITY;
        int   bA0 = 0,        bA1 = 0;

        const ulonglong2* pq = (const ulonglong2*)s_db + (size_t)myp0 * 4;
        for (int p = myp0; p < myp1; p++, pq += 4) {
            ull acc0 = 0ull, acc1 = 0ull;
            {   // k0..k3 (two LDS.128)
                const ulonglong2 q0 = pq[0];
                const ulonglong2 q1 = pq[1];
                acc0 = ffma2(q0.x, vka[0], acc0);  acc1 = ffma2(q0.x, vkb[0], acc1);
                acc0 = ffma2(q0.y, vka[1], acc0);  acc1 = ffma2(q0.y, vkb[1], acc1);
                acc0 = ffma2(q1.x, vka[2], acc0);  acc1 = ffma2(q1.x, vkb[2], acc1);
                acc0 = ffma2(q1.y, vka[3], acc0);  acc1 = ffma2(q1.y, vkb[3], acc1);
            }
            {   // k4..k7
                const ulonglong2 q2 = pq[2];
                const ulonglong2 q3 = pq[3];
                acc0 = ffma2(q2.x, vka[4], acc0);  acc1 = ffma2(q2.x, vkb[4], acc1);
                acc0 = ffma2(q2.y, vka[5], acc0);  acc1 = ffma2(q2.y, vkb[5], acc1);
                acc0 = ffma2(q3.x, vka[6], acc0);  acc1 = ffma2(q3.x, vkb[6], acc1);
                acc0 = ffma2(q3.y, vka[7], acc0);  acc1 = ffma2(q3.y, vkb[7], acc1);
            }
            const ull d2pair = *(const ull*)&s_d2[2 * p];
            const ull h0 = fadd2(d2pair, s2pa);
            const ull h1 = fadd2(d2pair, s2pb);
            const ull w0 = ffma2(neg2, acc0, h0);   // exact: 2*dot unrounded
            const ull w1 = ffma2(neg2, acc1, h1);
            float a, b, c, d;
            unpack2(w0, a, b); unpack2(w1, c, d);
            a = fmaxf(a, 0.f); b = fmaxf(b, 0.f);
            c = fmaxf(c, 0.f); d = fmaxf(d, 0.f);
            if (a < bU0) { bU0 = a; bA0 = 2 * p; }      // strict < -> first min
            if (b < bU0) { bU0 = b; bA0 = 2 * p + 1; }
            if (c < bU1) { bU1 = c; bA1 = 2 * p; }
            if (d < bU1) { bU1 = d; bA1 = 2 * p + 1; }
        }
        if (bA0 >= D) bA0 = D - 1;                      // pad lane = dup of last
        if (bA1 >= D) bA1 = D - 1;

        s_bu[grp * NPB + slot]         = bU0;  s_bi[grp * NPB + slot]         = bA0;
        s_bu[grp * NPB + slot + NSLOT] = bU1;  s_bi[grp * NPB + slot + NSLOT] = bA1;
        __syncthreads();

        if (grp == 0) {
#pragma unroll
            for (int w = 0; w < 2; w++) {
                const int sl = slot + w * NSLOT;
                const int n  = blockIdx.x * NPB + sl;
                if (n < Npix) {
                    float bu = s_bu[sl]; int bi = s_bi[sl];
#pragma unroll
                    for (int g = 1; g < NG; g++) {
                        const float u = s_bu[g * NPB + sl];
                        const int   i = s_bi[g * NPB + sl];
                        if (u < bu || (u == bu && i < bi)) { bu = u; bi = i; }
                    }
                    out[n]            = t2s[bi];
                    out[Npix + n]     = b1s[bi];
                    out[2 * Npix + n] = __fsqrt_rn(bu);
                }
            }
        }
    } else {
        // ================= K16 fallback (tiled, 512 threads) ==============
        constexpr int K = 16, TS = 512;
        float* s_db = (float*)smem_raw;          // TS*K floats
        float* s_d2 = s_db + TS * K;             // TS floats
        __syncthreads();                         // s_cols ready

        // Each thread handles 2 pixels to cover NPB-sized grid blocks.
        for (int w = 0; w < 2; w++) {
            const int n = blockIdx.x * NPB + w * THREADS + tid;
            const bool active = (n < Npix) && (w * THREADS + tid < NPB);
            if (w == 1 && THREADS >= NPB) break;

            float v[K]; float s2;
            prep_signal<K>(sig, n, active, etl, s_cols, s_ncols, v, s2);

            float bestU = INFINITY; int bestI = 0;
            for (int tile0 = 0; tile0 < D; tile0 += TS) {
                const int cnt = min(TS, D - tile0);
                __syncthreads();
                const float4* src = (const float4*)&g_db16[tile0 * K];
                float4* dst = (float4*)s_db;
                for (int idx = tid; idx < cnt * K / 4; idx += THREADS) dst[idx] = src[idx];
                for (int idx = tid; idx < cnt; idx += THREADS) s_d2[idx] = g_d2_16[tile0 + idx];
                __syncthreads();
                for (int aa = 0; aa < cnt; aa++) {
                    const float4* p = (const float4*)&s_db[aa * K];
                    float dot = 0.f;
#pragma unroll
                    for (int q = 0; q < K / 4; q++) {
                        float4 ww = p[q];
                        dot = __fmaf_rn(ww.x, v[4 * q + 0], dot);
                        dot = __fmaf_rn(ww.y, v[4 * q + 1], dot);
                        dot = __fmaf_rn(ww.z, v[4 * q + 2], dot);
                        dot = __fmaf_rn(ww.w, v[4 * q + 3], dot);
                    }
                    const float u = fmaxf(__fmaf_rn(-2.f, dot, __fadd_rn(s_d2[aa], s2)), 0.f);
                    if (u < bestU) { bestU = u; bestI = tile0 + aa; }
                }
            }
            if (active) {
                out[n]            = t2s[bestI];
                out[Npix + n]     = b1s[bestI];
                out[2 * Npix + n] = __fsqrt_rn(bestU);
            }
            __syncthreads();
        }
    }
}

// ---------------------------------------------------------------------------
extern "C" void kernel_launch(void* const* d_in, const int* in_sizes, int n_in,
                              void* d_out, int out_size) {
    const float* sig    = (const float*)d_in[0];
    const float* db_mag = (const float*)d_in[1];
    const float* t2s    = (const float*)d_in[2];
    const float* b1s    = (const float*)d_in[3];
    const float* delta  = (const float*)d_in[4];

    const int etl  = in_sizes[4];
    const int D    = in_sizes[1] / etl;
    const int Npix = in_sizes[0] / etl;
    float* out = (float*)d_out;

    // dynamic smem: max of K8 layout and K16 tile layout
    const int P = (D + 1) / 2;
    const size_t dyn8  = (size_t)(P * 16 + 2 * P + NG * NPB) * 4
                       + (size_t)(NG * NPB) * 4;
    const size_t dyn16 = (size_t)(512 * 16 + 512) * 4;
    const size_t dyn   = (dyn8 > dyn16) ? dyn8 : dyn16;
    cudaFuncSetAttribute(match_kernel,
                         cudaFuncAttributeMaxDynamicSharedMemorySize, (int)dyn);

    const int grid = (Npix + NPB - 1) / NPB;
    prep_kernel<<<32, 128>>>(delta, db_mag, D, etl);
    match_kernel<<<grid, THREADS, dyn>>>(sig, t2s, b1s, out, Npix, D, etl);
}

// round 11
// speedup vs baseline: 1.1544x; 1.0293x over previous
#include <cuda_runtime.h>
#include <math.h>

// DictionaryMatchingTv — bit-replicated fp32 nearest-atom search.
// R11: pair-level argmin (lane resolved post-loop by exact recompute) +
// unroll-4 on the pair loop. PX=2 @ 512 threads (R10-proven, no spill).

#define MAX_D   4096
#define MAX_ETL 16
#define NPB     256   // pixels per block
#define NSLOT   128   // pixel slots (each thread = 2 pixels: slot, slot+128)
#define NG      4     // dictionary chunks
#define THREADS 512   // NSLOT * NG

typedef unsigned long long ull;

__device__ int   g_cols[MAX_ETL];
__device__ int   g_ncols, g_kpad;

// K=8 path: pair-interleaved dict (a0k,a1k per k), flat d2 per atom (padded)
__device__ float g_dbp[((MAX_D + 1) / 2) * 16];
__device__ float g_d2p[MAX_D + 1];

// K=16 fallback path
__device__ float g_db16[MAX_D * MAX_ETL];
__device__ float g_d2_16[MAX_D];

// ---- packed f32x2 helpers (per-lane IEEE rn, identical to scalar) --------
__device__ __forceinline__ ull pack2(float lo, float hi) {
    ull r; asm("mov.b64 %0, {%1, %2};" : "=l"(r) : "f"(lo), "f"(hi)); return r;
}
__device__ __forceinline__ void unpack2(ull v, float& lo, float& hi) {
    asm("mov.b64 {%0, %1}, %2;" : "=f"(lo), "=f"(hi) : "l"(v));
}
__device__ __forceinline__ ull ffma2(ull a, ull b, ull c) {
    ull d; asm("fma.rn.f32x2 %0, %1, %2, %3;" : "=l"(d) : "l"(a), "l"(b), "l"(c)); return d;
}
__device__ __forceinline__ ull fadd2(ull a, ull b) {
    ull d; asm("add.rn.f32x2 %0, %1, %2;" : "=l"(d) : "l"(a), "l"(b)); return d;
}

// ---------------------------------------------------------------------------
// Mask via warp ballot (order = ascending lane == serial scan).
// ---------------------------------------------------------------------------
__device__ __forceinline__ void ballot_mask(const float* __restrict__ delta,
                                            int etl, int* s_cols, int* s_ncols) {
    const int lane = threadIdx.x;             // caller guarantees tid < 32
    bool p = false;
    if (lane < etl && lane < MAX_ETL)
        p = (__fmul_rn(delta[lane], 1e-3f) < 1e-3f);
    const unsigned m = __ballot_sync(0xffffffffu, p);
    if (p) s_cols[__popc(m & ((1u << lane) - 1u))] = lane;
    if (lane == 0) *s_ncols = __popc(m);
}

// ---------------------------------------------------------------------------
// Prep (parallel): mask + normalize + pair-interleave.
// ---------------------------------------------------------------------------
__global__ void __launch_bounds__(128)
prep_kernel(const float* __restrict__ delta, const float* __restrict__ db_mag,
            int D, int etl) {
    __shared__ int s_cols[MAX_ETL];
    __shared__ int s_ncols;
    if (threadIdx.x < 32) ballot_mask(delta, etl, s_cols, &s_ncols);
    __syncthreads();
    const int ncols = s_ncols;
    const int kp    = (ncols <= 8) ? 8 : 16;
    if (blockIdx.x == 0 && threadIdx.x == 0) {
        for (int k = 0; k < ncols; k++) g_cols[k] = s_cols[k];
        g_ncols = ncols;
        g_kpad  = kp;
    }
    const int Dpad = (D + 1) & ~1;

    for (int a = blockIdx.x * blockDim.x + threadIdx.x; a < Dpad;
         a += gridDim.x * blockDim.x) {
        const int d = (a < D) ? a : D - 1;          // pad = duplicate last atom
        float x[MAX_ETL];
#pragma unroll
        for (int k = 0; k < MAX_ETL; k++)
            x[k] = (k < ncols) ? db_mag[d * etl + s_cols[k]] : 0.f;
        float ss = 0.f;
#pragma unroll
        for (int k = 0; k < MAX_ETL; k++) ss = __fadd_rn(ss, __fmul_rn(x[k], x[k]));
        const float nn = __fsqrt_rn(ss);
        float v[MAX_ETL]; float d2 = 0.f;
#pragma unroll
        for (int k = 0; k < MAX_ETL; k++) {
            v[k] = (nn > 0.f) ? __fdiv_rn(x[k], nn) : 0.f;
            d2 = __fadd_rn(d2, __fmul_rn(v[k], v[k]));
        }
        if (kp == 8) {
            const int base = (a >> 1) * 16 + (a & 1);
#pragma unroll
            for (int k = 0; k < 8; k++) g_dbp[base + 2 * k] = v[k];
            g_d2p[a] = d2;
        } else if (a < D) {
#pragma unroll
            for (int k = 0; k < MAX_ETL; k++) g_db16[d * MAX_ETL + k] = v[k];
            g_d2_16[d] = d2;
        }
    }
}

// ---------------------------------------------------------------------------
// Signal prep (two-stage normalization, exact fp32 replication).
// ---------------------------------------------------------------------------
template <int K>
__device__ __forceinline__ void prep_signal(const float* __restrict__ sig,
                                            int n, bool active, int etl,
                                            const int* s_cols, int ncols,
                                            float* v, float& s2) {
    float raw[MAX_ETL];
#pragma unroll
    for (int e = 0; e < MAX_ETL; e++)
        raw[e] = (active && e < etl) ? sig[n * etl + e] : 0.f;
    float ss1 = 0.f;
#pragma unroll
    for (int e = 0; e < MAX_ETL; e++) ss1 = __fadd_rn(ss1, __fmul_rn(raw[e], raw[e]));
    const float n1 = __fsqrt_rn(ss1);
    float t[K];
#pragma unroll
    for (int k = 0; k < K; k++) {
        t[k] = 0.f;
        if (k < ncols) t[k] = (n1 > 0.f) ? __fdiv_rn(raw[s_cols[k]], n1) : 0.f;
    }
    float ss2 = 0.f;
#pragma unroll
    for (int k = 0; k < K; k++) ss2 = __fadd_rn(ss2, __fmul_rn(t[k], t[k]));
    const float n2 = __fsqrt_rn(ss2);
#pragma unroll
    for (int k = 0; k < K; k++) v[k] = (n2 > 0.f) ? __fdiv_rn(t[k], n2) : 0.f;
    s2 = 0.f;
#pragma unroll
    for (int k = 0; k < K; k++) s2 = __fadd_rn(s2, __fmul_rn(v[k], v[k]));
}

// Recompute one pair's clamped distances for a pixel (bit-identical to the
// hot loop) and resolve the winning atom index with first-min tie-break.
__device__ __forceinline__ int resolve_lane(const float* s_db, const float* s_d2,
                                            int bP, const ull* vk, ull s2p,
                                            ull neg2, float bU) {
    const ulonglong2* pr = (const ulonglong2*)s_db + (size_t)bP * 4;
    const ulonglong2 q0 = pr[0], q1 = pr[1], q2 = pr[2], q3 = pr[3];
    ull acc = 0ull;
    acc = ffma2(q0.x, vk[0], acc);
    acc = ffma2(q0.y, vk[1], acc);
    acc = ffma2(q1.x, vk[2], acc);
    acc = ffma2(q1.y, vk[3], acc);
    acc = ffma2(q2.x, vk[4], acc);
    acc = ffma2(q2.y, vk[5], acc);
    acc = ffma2(q3.x, vk[6], acc);
    acc = ffma2(q3.y, vk[7], acc);
    const ull h = fadd2(*(const ull*)&s_d2[2 * bP], s2p);
    const ull w = ffma2(neg2, acc, h);
    float a, b; unpack2(w, a, b);
    a = fmaxf(a, 0.f);
    return 2 * bP + ((a == bU) ? 0 : 1);   // lane0 wins ties (first-min)
}

// ---------------------------------------------------------------------------
// Fused worker: one launch, internal K8/K16 dispatch.
// ---------------------------------------------------------------------------
__global__ void __launch_bounds__(THREADS, 1)
match_kernel(const float* __restrict__ sig,
             const float* __restrict__ t2s,
             const float* __restrict__ b1s,
             float* __restrict__ out,
             int Npix, int D, int etl) {
    extern __shared__ char smem_raw[];
    __shared__ int s_cols[MAX_ETL];
    __shared__ int s_ncols;

    const int tid = threadIdx.x;
    if (tid < MAX_ETL) s_cols[tid] = g_cols[tid];
    if (tid == 0) s_ncols = g_ncols;

    if (g_kpad == 8) {
        // ================= K8 path: 512 thr = 128 slots x 2 px x 4 chunks ==
        const int P = (D + 1) >> 1;             // atom pairs (padded)
        float* s_db = (float*)smem_raw;         // P*16 floats, pair-interleaved
        float* s_d2 = s_db + P * 16;            // 2*P floats
        float* s_bu = s_d2 + 2 * P;             // NG*NPB
        int*   s_bi = (int*)(s_bu + NG * NPB);  // NG*NPB

        const int slot = tid & (NSLOT - 1);     // 0..127
        const int grp  = tid >> 7;              // 0..3

        {
            const float4* src = (const float4*)g_dbp;
            float4* dst = (float4*)s_db;
            for (int i = tid; i < P * 4; i += THREADS) dst[i] = src[i];
            for (int i = tid; i < 2 * P; i += THREADS) s_d2[i] = g_d2p[i];
        }
        __syncthreads();

        const int n0 = blockIdx.x * NPB + slot;        // pixel A
        const int n1 = n0 + NSLOT;                     // pixel B
        const bool act0 = (n0 < Npix);
        const bool act1 = (n1 < Npix);

        float va[8], vb[8], s2a, s2b;
        prep_signal<8>(sig, n0, act0, etl, s_cols, s_ncols, va, s2a);
        prep_signal<8>(sig, n1, act1, etl, s_cols, s_ncols, vb, s2b);
        ull vka[8], vkb[8];
#pragma unroll
        for (int k = 0; k < 8; k++) { vka[k] = pack2(va[k], va[k]); vkb[k] = pack2(vb[k], vb[k]); }
        const ull s2pa = pack2(s2a, s2a);
        const ull s2pb = pack2(s2b, s2b);
        const ull neg2 = pack2(-2.f, -2.f);
        __syncthreads();

        const int Lp   = (P + NG - 1) / NG;
        const int myp0 = grp * Lp;
        const int myp1 = min(myp0 + Lp, P);

        float bU0 = INFINITY, bU1 = INFINITY;
        int   bP0 = myp0,     bP1 = myp0;

        const ulonglong2* pq = (const ulonglong2*)s_db + (size_t)myp0 * 4;
#pragma unroll 4
        for (int p = myp0; p < myp1; p++, pq += 4) {
            const ulonglong2 q0 = pq[0];
            const ulonglong2 q1 = pq[1];
            const ulonglong2 q2 = pq[2];
            const ulonglong2 q3 = pq[3];
            ull acc0 = 0ull, acc1 = 0ull;
            acc0 = ffma2(q0.x, vka[0], acc0);  acc1 = ffma2(q0.x, vkb[0], acc1);
            acc0 = ffma2(q0.y, vka[1], acc0);  acc1 = ffma2(q0.y, vkb[1], acc1);
            acc0 = ffma2(q1.x, vka[2], acc0);  acc1 = ffma2(q1.x, vkb[2], acc1);
            acc0 = ffma2(q1.y, vka[3], acc0);  acc1 = ffma2(q1.y, vkb[3], acc1);
            acc0 = ffma2(q2.x, vka[4], acc0);  acc1 = ffma2(q2.x, vkb[4], acc1);
            acc0 = ffma2(q2.y, vka[5], acc0);  acc1 = ffma2(q2.y, vkb[5], acc1);
            acc0 = ffma2(q3.x, vka[6], acc0);  acc1 = ffma2(q3.x, vkb[6], acc1);
            acc0 = ffma2(q3.y, vka[7], acc0);  acc1 = ffma2(q3.y, vkb[7], acc1);
            const ull d2pair = *(const ull*)&s_d2[2 * p];
            const ull h0 = fadd2(d2pair, s2pa);
            const ull h1 = fadd2(d2pair, s2pb);
            const ull w0 = ffma2(neg2, acc0, h0);   // exact: 2*dot unrounded
            const ull w1 = ffma2(neg2, acc1, h1);
            float a, b, c, d;
            unpack2(w0, a, b); unpack2(w1, c, d);
            a = fmaxf(a, 0.f); b = fmaxf(b, 0.f);
            c = fmaxf(c, 0.f); d = fmaxf(d, 0.f);
            const float m0 = fminf(a, b);
            const float m1 = fminf(c, d);
            if (m0 < bU0) bP0 = p;                  // strict < -> first pair
            bU0 = fminf(bU0, m0);
            if (m1 < bU1) bP1 = p;
            bU1 = fminf(bU1, m1);
        }

        // Resolve winning lane within the best pair (exact recompute).
        int bA0 = resolve_lane(s_db, s_d2, bP0, vka, s2pa, neg2, bU0);
        int bA1 = resolve_lane(s_db, s_d2, bP1, vkb, s2pb, neg2, bU1);
        if (bA0 >= D) bA0 = D - 1;                  // pad lane = dup of last
        if (bA1 >= D) bA1 = D - 1;

        s_bu[grp * NPB + slot]         = bU0;  s_bi[grp * NPB + slot]         = bA0;
        s_bu[grp * NPB + slot + NSLOT] = bU1;  s_bi[grp * NPB + slot + NSLOT] = bA1;
        __syncthreads();

        if (grp == 0) {
#pragma unroll
            for (int w = 0; w < 2; w++) {
                const int sl = slot + w * NSLOT;
                const int n  = blockIdx.x * NPB + sl;
                if (n < Npix) {
                    float bu = s_bu[sl]; int bi = s_bi[sl];
#pragma unroll
                    for (int g = 1; g < NG; g++) {
                        const float u = s_bu[g * NPB + sl];
                        const int   i = s_bi[g * NPB + sl];
                        if (u < bu || (u == bu && i < bi)) { bu = u; bi = i; }
                    }
                    out[n]            = t2s[bi];
                    out[Npix + n]     = b1s[bi];
                    out[2 * Npix + n] = __fsqrt_rn(bu);
                }
            }
        }
    } else {
        // ================= K16 fallback (tiled, 512 threads) ==============
        constexpr int K = 16, TS = 512;
        float* s_db = (float*)smem_raw;          // TS*K floats
        float* s_d2 = s_db + TS * K;             // TS floats
        __syncthreads();                         // s_cols ready

        for (int w = 0; w < 2; w++) {
            const int n = blockIdx.x * NPB + w * THREADS + tid;
            const bool active = (n < Npix) && (w * THREADS + tid < NPB);
            if (w == 1 && THREADS >= NPB) break;

            float v[K]; float s2;
            prep_signal<K>(sig, n, active, etl, s_cols, s_ncols, v, s2);

            float bestU = INFINITY; int bestI = 0;
            for (int tile0 = 0; tile0 < D; tile0 += TS) {
                const int cnt = min(TS, D - tile0);
                __syncthreads();
                const float4* src = (const float4*)&g_db16[tile0 * K];
                float4* dst = (float4*)s_db;
                for (int idx = tid; idx < cnt * K / 4; idx += THREADS) dst[idx] = src[idx];
                for (int idx = tid; idx < cnt; idx += THREADS) s_d2[idx] = g_d2_16[tile0 + idx];
                __syncthreads();
                for (int aa = 0; aa < cnt; aa++) {
                    const float4* p = (const float4*)&s_db[aa * K];
                    float dot = 0.f;
#pragma unroll
                    for (int q = 0; q < K / 4; q++) {
                        float4 ww = p[q];
                        dot = __fmaf_rn(ww.x, v[4 * q + 0], dot);
                        dot = __fmaf_rn(ww.y, v[4 * q + 1], dot);
                        dot = __fmaf_rn(ww.z, v[4 * q + 2], dot);
                        dot = __fmaf_rn(ww.w, v[4 * q + 3], dot);
                    }
                    const float u = fmaxf(__fmaf_rn(-2.f, dot, __fadd_rn(s_d2[aa], s2)), 0.f);
                    if (u < bestU) { bestU = u; bestI = tile0 + aa; }
                }
            }
            if (active) {
                out[n]            = t2s[bestI];
                out[Npix + n]     = b1s[bestI];
                out[2 * Npix + n] = __fsqrt_rn(bestU);
            }
            __syncthreads();
        }
    }
}

// ---------------------------------------------------------------------------
extern "C" void kernel_launch(void* const* d_in, const int* in_sizes, int n_in,
                              void* d_out, int out_size) {
    const float* sig    = (const float*)d_in[0];
    const float* db_mag = (const float*)d_in[1];
    const float* t2s    = (const float*)d_in[2];
    const float* b1s    = (const float*)d_in[3];
    const float* delta  = (const float*)d_in[4];

    const int etl  = in_sizes[4];
    const int D    = in_sizes[1] / etl;
    const int Npix = in_sizes[0] / etl;
    float* out = (float*)d_out;

    // dynamic smem: max of K8 layout and K16 tile layout
    const int P = (D + 1) / 2;
    const size_t dyn8  = (size_t)(P * 16 + 2 * P + NG * NPB) * 4
                       + (size_t)(NG * NPB) * 4;
    const size_t dyn16 = (size_t)(512 * 16 + 512) * 4;
    const size_t dyn   = (dyn8 > dyn16) ? dyn8 : dyn16;
    cudaFuncSetAttribute(match_kernel,
                         cudaFuncAttributeMaxDynamicSharedMemorySize, (int)dyn);

    const int grid = (Npix + NPB - 1) / NPB;
    prep_kernel<<<32, 128>>>(delta, db_mag, D, etl);
    match_kernel<<<grid, THREADS, dyn>>>(sig, t2s, b1s, out, Npix, D, etl);
}